// round 11
// baseline (speedup 1.0000x reference)
#include <cuda_runtime.h>
#include <math.h>

// Fixed shapes: B=4096, NSPIN=2, NPS=16, D=256, NION=8, DIM=3
#define BMAX 4096
typedef unsigned long long ull;

// ---------------- f32x2 helpers (packed dual-FMA, sm_100+) ----------------
__device__ __forceinline__ ull fsplat(float a) {
    ull r; asm("mov.b64 %0, {%1, %1};" : "=l"(r) : "f"(a)); return r;
}
__device__ __forceinline__ ull fma2(ull a, ull b, ull c) {
    ull d; asm("fma.rn.f32x2 %0, %1, %2, %3;" : "=l"(d) : "l"(a), "l"(b), "l"(c)); return d;
}
__device__ __forceinline__ float pklo(ull v) { return __uint_as_float((unsigned)v); }
__device__ __forceinline__ float pkhi(ull v) { return __uint_as_float((unsigned)(v >> 32)); }

#define CP16(dst, src) \
    asm volatile("cp.async.cg.shared.global [%0], [%1], 16;" :: "r"(dst), "l"(src))

// Dynamic smem layout (floats):
//   sX: [2][128 rows][32]  XOR-swizzled  ->  8192 floats (32768 B)
//        (buffer 0 reused after GEMM as sM[128][17] + pivot buffers)
//   sW: [2][256][16]                      ->  8192 floats (32768 B)
//   sG: [256][8]                          ->  2048 floats ( 8192 B)
#define SMEM_FLOATS (8192 + 8192 + 2048)
#define SMEM_BYTES  (SMEM_FLOATS * 4)     // 73728 B -> 3 CTAs/SM

// ---------------------------------------------------------------------------
// Fully fused kernel, 4 batches / CTA, thread tile = 1 row x 8 cols:
//   phase 1: y = x@W + b, env, M = y*env   (M staged in smem, stride-17 rows)
//   phase 2: per (b,s) 16x16 matrix, cof_i = M[i,0]*det(M)*(M^{-1})_{0,i}
//            fp32 Gauss-Jordan w/ virtual partial pivoting, one matrix per
//            16-lane half-warp (8 matrices -> warps 0..3).
// ---------------------------------------------------------------------------
__global__ __launch_bounds__(256, 3) void fused_kernel(
    const float* __restrict__ X,      // [B][32][256]
    const float* __restrict__ R,      // [B][32][8][3]
    const float* __restrict__ W,      // [2][256][16]
    const float* __restrict__ Bias,   // [2][16]
    const float* __restrict__ ED,     // [2][8][16][3][3]
    const float* __restrict__ EI,     // [2][8][16]
    float* __restrict__ out)          // [B*2][16]
{
    extern __shared__ float smem[];
    float* sX = smem;             // swizzled X tiles (2 x 4096 floats)
    float* sW = smem + 8192;      // full W
    float* sG = smem + 16384;     // G table
    float* sM = smem;             // phase-2 alias: M[128 local rows][17]
    float* sP = smem + 128 * 17;  // phase-2 pivot buffers [8][18]

    const int tid  = threadIdx.x;
    const int blk  = blockIdx.x;
    const int row  = tid >> 1;          // local row 0..127 (= b_local*32 + sn)
    const int cgh  = tid & 1;           // column half: cols 8*cgh .. 8*cgh+7
    const int s    = (row >> 4) & 1;    // spin of this row

    const unsigned sXaddr = (unsigned)__cvta_generic_to_shared(sX);
    const unsigned sWaddr = (unsigned)__cvta_generic_to_shared(sW);

    const float* Xblk = X + (size_t)blk * 32768;   // 4 batches * 32 rows * 256

    // --- prologue: async-copy full W (8192 floats) + X chunk 0 ---
#pragma unroll
    for (int it = 0; it < 8; it++) {
        int c = it * 256 + tid;                       // 2048 16B granules
        CP16(sWaddr + c * 16, W + c * 4);
    }
#pragma unroll
    for (int it = 0; it < 4; it++) {
        int idx = it * 256 + tid;                     // 1024 granules
        int r = idx >> 3, dq = idx & 7;
        CP16(sXaddr + (r << 7) + ((dq ^ (r & 7)) << 4), Xblk + r * 256 + dq * 4);
    }
    asm volatile("cp.async.commit_group;");

    // --- G = A^T A per (s,i,o), one entry per thread (overlaps cp.async) ---
    {
        const float* A = ED + tid * 9;
        float a00=A[0],a01=A[1],a02=A[2];
        float a10=A[3],a11=A[4],a12=A[5];
        float a20=A[6],a21=A[7],a22=A[8];
        float* gp = sG + tid * 8;
        gp[0] = a00*a00 + a10*a10 + a20*a20;
        gp[1] = a01*a01 + a11*a11 + a21*a21;
        gp[2] = a02*a02 + a12*a12 + a22*a22;
        gp[3] = 2.0f*(a00*a01 + a10*a11 + a20*a21);
        gp[4] = 2.0f*(a00*a02 + a10*a12 + a20*a22);
        gp[5] = 2.0f*(a01*a02 + a11*a12 + a21*a22);
        gp[6] = EI[tid];
        gp[7] = 0.0f;
    }

    // acc[p]: packed (col 8cgh+2p, col 8cgh+2p+1) accumulators for this row
    ull acc[4];
#pragma unroll
    for (int p = 0; p < 4; p++) acc[p] = 0ull;

    const int xkey = row & 7;

#pragma unroll 1
    for (int ch = 0; ch < 8; ch++) {
        if (ch < 7) {
            const float* src   = Xblk + (ch + 1) * 32;
            unsigned     dbase = sXaddr + ((unsigned)((ch + 1) & 1)) * 16384u;
#pragma unroll
            for (int it = 0; it < 4; it++) {
                int idx = it * 256 + tid;
                int r = idx >> 3, dq = idx & 7;
                CP16(dbase + (r << 7) + ((dq ^ (r & 7)) << 4), src + r * 256 + dq * 4);
            }
            asm volatile("cp.async.commit_group;");
            asm volatile("cp.async.wait_group 1;");
        } else {
            asm volatile("cp.async.wait_group 0;");
        }
        __syncthreads();

        const float* xb = sX + (ch & 1) * 4096;
        const float* wb = sW + s * 4096 + ch * 512;   // chunk d0 = ch*32
#pragma unroll
        for (int d4 = 0; d4 < 8; d4++) {
            float4 xq = *(const float4*)(xb + (row << 5) + ((d4 ^ xkey) << 2));
#pragma unroll
            for (int dd = 0; dd < 4; dd++) {
                const float* wp = wb + (d4 * 4 + dd) * 16 + (cgh << 3);
                ull w01 = ((const ull*)wp)[0];
                ull w23 = ((const ull*)wp)[1];
                ull w45 = ((const ull*)wp)[2];
                ull w67 = ((const ull*)wp)[3];
                float xv = (dd == 0) ? xq.x : (dd == 1) ? xq.y
                         : (dd == 2) ? xq.z : xq.w;
                ull xs = fsplat(xv);
                acc[0] = fma2(xs, w01, acc[0]);
                acc[1] = fma2(xs, w23, acc[1]);
                acc[2] = fma2(xs, w45, acc[2]);
                acc[3] = fma2(xs, w67, acc[3]);
            }
        }
        __syncthreads();
    }
    // Final barrier above: all GEMM reads of sX done -> buffer 0 reusable as sM.
    // (Last chunk computed from buffer 1, so writing buffer 0 needs no barrier.)

    // --- Envelope + M assembly: write this row's 8 columns into smem ---
    {
        const float4* rp = (const float4*)(R + ((size_t)blk * 128 + row) * 24);
        float rv[24];
#pragma unroll
        for (int q = 0; q < 6; q++) {
            float4 t = rp[q];
            rv[q*4+0] = t.x; rv[q*4+1] = t.y; rv[q*4+2] = t.z; rv[q*4+3] = t.w;
        }
        float env[8];
#pragma unroll
        for (int j = 0; j < 8; j++) env[j] = 0.0f;
#pragma unroll
        for (int i = 0; i < 8; i++) {
            float px = rv[i*3 + 0];
            float py = rv[i*3 + 1];
            float pz = rv[i*3 + 2];
#pragma unroll
            for (int cj = 0; cj < 8; cj++) {
                int gi = s * 128 + i * 16 + (cgh << 3) + cj;
                float4 ga = *(const float4*)(sG + gi * 8);      // gxx,gyy,gzz,2gxy
                float4 gb = *(const float4*)(sG + gi * 8 + 4);  // 2gxz,2gyz,ion,pad
                float q1 = px * (ga.x * px + ga.w * py + gb.x * pz)
                         + py * (ga.y * py + gb.y * pz)
                         + pz * (ga.z * pz);
                float rl;
                asm("sqrt.approx.f32 %0, %1;" : "=f"(rl) : "f"(q1));
                env[cj] += __expf(-rl) * gb.z;
            }
        }
        float* mrow = sM + row * 17 + (cgh << 3);
        const float* bp = Bias + s * 16 + (cgh << 3);
#pragma unroll
        for (int p = 0; p < 4; p++) {
            mrow[2*p + 0] = (pklo(acc[p]) + bp[2*p + 0]) * env[2*p + 0];
            mrow[2*p + 1] = (pkhi(acc[p]) + bp[2*p + 1]) * env[2*p + 1];
        }
    }
    __syncthreads();

    // ======================= phase 2: cofactors ===========================
    // 8 matrices (4 batches x 2 spins); matrix lmat rows at sM[lmat*16+n][.].
    // One matrix per 16-lane half-warp -> warps 0..3 (threads 0..127).
    if (tid < 128) {
        const unsigned FULL = 0xffffffffu;
        const int lmat = tid >> 4;
        const int r    = tid & 15;                 // row of A (= column of M)
        const unsigned hmask = 0xFFFFu << (tid & 16);
        float* pb = sP + lmat * 18;
        const float* Mb = sM + lmat * 16 * 17;     // this matrix's 16 rows

        float a[16];
#pragma unroll
        for (int c = 0; c < 16; c++) a[c] = Mb[c * 17 + r];  // A[r][c] = M[c][r]
        float rhs = (r == 0) ? 1.0f : 0.0f;
        float mi0 = Mb[r * 17];                    // M[r][0]

        float det = 1.0f;
        int  sstep = 16;
        int  myp   = 0;
        bool elim  = false;

#pragma unroll
        for (int k = 0; k < 16; k++) {
            unsigned keyv = 0u;
            if (!elim) {
                unsigned mb = __float_as_uint(fabsf(a[k]));
                keyv = (mb & 0xFFFFFFE0u) | 0x10u | (unsigned)r;
            }
            unsigned best = __reduce_max_sync(hmask, keyv);
            int p = (int)(best & 15u);
            if (k == r) myp = p;
            bool ispiv = (r == p);

            if (ispiv) {
                float pv  = a[k];
                float inv = 1.0f / pv;
                pb[17] = pv;
#pragma unroll
                for (int c = k + 1; c < 16; c++) { a[c] *= inv; pb[c] = a[c]; }
                rhs *= inv;
                pb[16] = rhs;
                elim  = true;
                sstep = k;
            }
            __syncwarp(FULL);

            det *= pb[17];

            if (!ispiv) {
                float f = a[k];
#pragma unroll
                for (int c = k + 1; c < 16; c++) a[c] = fmaf(-f, pb[c], a[c]);
                rhs = fmaf(-f, pb[16], rhs);
            }
            __syncwarp(FULL);
        }

        // Permutation parity via inversion count of sstep sequence
        int invc = 0;
#pragma unroll
        for (int j = 0; j < 16; j++) {
            int sj = __shfl_sync(FULL, sstep, j, 16);
            if (j > r && sj < sstep) invc++;
        }
#pragma unroll
        for (int off = 8; off > 0; off >>= 1) invc += __shfl_xor_sync(FULL, invc, off, 16);
        if (invc & 1) det = -det;

        float z = __shfl_sync(FULL, rhs, myp, 16);

        out[((size_t)blk * 8 + lmat) * 16 + r] = mi0 * det * z;
    }
}

// ---------------------------------------------------------------------------
extern "C" void kernel_launch(void* const* d_in, const int* in_sizes, int n_in,
                              void* d_out, int out_size) {
    const float* X    = (const float*)d_in[0];   // eq_inputs [B][32][256]
    const float* R    = (const float*)d_in[1];   // r_ei      [B][32][8][3]
    const float* W    = (const float*)d_in[2];   // W         [2][256][16]
    const float* Bias = (const float*)d_in[3];   // b         [2][16]
    const float* ED   = (const float*)d_in[4];   // env_dim   [2][8][16][3][3]
    const float* EI   = (const float*)d_in[5];   // env_ion   [2][8][16]
    float* out = (float*)d_out;

    int B = in_sizes[0] / (32 * 256);            // 4096
    if (B > BMAX) B = BMAX;

    // Idempotent attribute set for >48KB dynamic smem (no allocation involved)
    cudaFuncSetAttribute(fused_kernel,
                         cudaFuncAttributeMaxDynamicSharedMemorySize, SMEM_BYTES);

    fused_kernel<<<B / 4, 256, SMEM_BYTES>>>(X, R, W, Bias, ED, EI, out);
    (void)n_in; (void)out_size;
}

// round 12
// speedup vs baseline: 1.0622x; 1.0622x over previous
#include <cuda_runtime.h>
#include <math.h>

// Fixed shapes: B=4096, NSPIN=2, NPS=16, D=256, NION=8, DIM=3
#define BMAX 4096
typedef unsigned long long ull;

// ---------------- f32x2 helpers (packed dual-FMA, sm_100+) ----------------
__device__ __forceinline__ ull fsplat(float a) {
    ull r; asm("mov.b64 %0, {%1, %1};" : "=l"(r) : "f"(a)); return r;
}
__device__ __forceinline__ ull fma2(ull a, ull b, ull c) {
    ull d; asm("fma.rn.f32x2 %0, %1, %2, %3;" : "=l"(d) : "l"(a), "l"(b), "l"(c)); return d;
}
__device__ __forceinline__ float pklo(ull v) { return __uint_as_float((unsigned)v); }
__device__ __forceinline__ float pkhi(ull v) { return __uint_as_float((unsigned)(v >> 32)); }

#define CP16(dst, src) \
    asm volatile("cp.async.cg.shared.global [%0], [%1], 16;" :: "r"(dst), "l"(src))

// Dynamic smem layout (floats):
//   sX: [2][128 rows][32]  XOR-swizzled (key=(r>>1)&7) -> 8192 floats (32768 B)
//        (buffer 0 reused after GEMM as sM[128][17] + pivot buffers)
//   sW: [2][256][16]                      ->  8192 floats (32768 B)
//   sG: [256][8]                          ->  2048 floats ( 8192 B)
#define SMEM_FLOATS (8192 + 8192 + 2048)
#define SMEM_BYTES  (SMEM_FLOATS * 4)     // 73728 B -> 3 CTAs/SM

// ---------------------------------------------------------------------------
// Fully fused kernel, 4 batches / CTA, thread tile = 2 rows x 4 cols:
//   phase 1: y = x@W + b, env, M = y*env   (M staged in smem, stride-17 rows)
//   phase 2: per (b,s) 16x16 matrix, cof_i = M[i,0]*det(M)*(M^{-1})_{0,i}
//            fp32 Gauss-Jordan w/ virtual partial pivoting, one matrix per
//            16-lane half-warp (8 matrices -> warps 0..3).
// ---------------------------------------------------------------------------
__global__ __launch_bounds__(256, 3) void fused_kernel(
    const float* __restrict__ X,      // [B][32][256]
    const float* __restrict__ R,      // [B][32][8][3]
    const float* __restrict__ W,      // [2][256][16]
    const float* __restrict__ Bias,   // [2][16]
    const float* __restrict__ ED,     // [2][8][16][3][3]
    const float* __restrict__ EI,     // [2][8][16]
    float* __restrict__ out)          // [B*2][16]
{
    extern __shared__ float smem[];
    float* sX = smem;             // swizzled X tiles (2 x 4096 floats)
    float* sW = smem + 8192;      // full W
    float* sG = smem + 16384;     // G table
    float* sM = smem;             // phase-2 alias: M[128 local rows][17]
    float* sP = smem + 128 * 17;  // phase-2 pivot buffers [8][18]

    const int tid  = threadIdx.x;
    const int blk  = blockIdx.x;
    const int q    = tid >> 2;          // row-pair index 0..63
    const int cg   = tid & 3;           // column group: cols 4cg..4cg+3
    const int row0 = q << 1;            // rows row0, row0+1 (same spin block)
    const int s    = (row0 >> 4) & 1;   // spin of both rows

    const unsigned sXaddr = (unsigned)__cvta_generic_to_shared(sX);
    const unsigned sWaddr = (unsigned)__cvta_generic_to_shared(sW);

    const float* Xblk = X + (size_t)blk * 32768;   // 4 batches * 32 rows * 256

    // --- prologue: async-copy full W (8192 floats) + X chunk 0 ---
#pragma unroll
    for (int it = 0; it < 8; it++) {
        int c = it * 256 + tid;                       // 2048 16B granules
        CP16(sWaddr + c * 16, W + c * 4);
    }
#pragma unroll
    for (int it = 0; it < 4; it++) {
        int idx = it * 256 + tid;                     // 1024 granules
        int r = idx >> 3, dq = idx & 7;
        CP16(sXaddr + (r << 7) + ((dq ^ ((r >> 1) & 7)) << 4),
             Xblk + r * 256 + dq * 4);
    }
    asm volatile("cp.async.commit_group;");

    // --- G = A^T A per (s,i,o), one entry per thread (overlaps cp.async) ---
    {
        const float* A = ED + tid * 9;
        float a00=A[0],a01=A[1],a02=A[2];
        float a10=A[3],a11=A[4],a12=A[5];
        float a20=A[6],a21=A[7],a22=A[8];
        float* gp = sG + tid * 8;
        gp[0] = a00*a00 + a10*a10 + a20*a20;
        gp[1] = a01*a01 + a11*a11 + a21*a21;
        gp[2] = a02*a02 + a12*a12 + a22*a22;
        gp[3] = 2.0f*(a00*a01 + a10*a11 + a20*a21);
        gp[4] = 2.0f*(a00*a02 + a10*a12 + a20*a22);
        gp[5] = 2.0f*(a01*a02 + a11*a12 + a21*a22);
        gp[6] = EI[tid];
        gp[7] = 0.0f;
    }

    // acc[ri][p]: packed (col 4cg+2p, 4cg+2p+1) accumulators, ri = row in pair
    ull acc[2][2];
    acc[0][0] = 0ull; acc[0][1] = 0ull; acc[1][0] = 0ull; acc[1][1] = 0ull;

    const int xkey = q & 7;             // = (row0>>1)&7, same for both rows

#pragma unroll 1
    for (int ch = 0; ch < 8; ch++) {
        // Chunk ch was committed in the previous iteration (or prologue);
        // its DMA latency was covered by the previous chunk's compute.
        asm volatile("cp.async.wait_group 0;");
        __syncthreads();
        // Race-free prefetch: everyone is past the barrier, so buffer
        // (ch+1)&1 (which held chunk ch-1) has no remaining readers.
        if (ch < 7) {
            const float* src   = Xblk + (ch + 1) * 32;
            unsigned     dbase = sXaddr + ((unsigned)((ch + 1) & 1)) * 16384u;
#pragma unroll
            for (int it = 0; it < 4; it++) {
                int idx = it * 256 + tid;
                int r = idx >> 3, dq = idx & 7;
                CP16(dbase + (r << 7) + ((dq ^ ((r >> 1) & 7)) << 4),
                     src + r * 256 + dq * 4);
            }
            asm volatile("cp.async.commit_group;");
        }

        const float* xb = sX + (ch & 1) * 4096;
        const float* wb = sW + s * 4096 + ch * 512;   // chunk d0 = ch*32
#pragma unroll
        for (int d4 = 0; d4 < 8; d4++) {
            const int xoff = ((d4 ^ xkey) << 2);
            float4 xq0 = *(const float4*)(xb + (row0 << 5) + xoff);
            float4 xq1 = *(const float4*)(xb + ((row0 + 1) << 5) + xoff);
#pragma unroll
            for (int dd = 0; dd < 4; dd++) {
                // One LDS.128: this thread's 4 W columns for depth d
                ulonglong2 wv = *(const ulonglong2*)(wb + (d4 * 4 + dd) * 16 + (cg << 2));
                float x0 = (dd == 0) ? xq0.x : (dd == 1) ? xq0.y
                         : (dd == 2) ? xq0.z : xq0.w;
                float x1 = (dd == 0) ? xq1.x : (dd == 1) ? xq1.y
                         : (dd == 2) ? xq1.z : xq1.w;
                ull xs0 = fsplat(x0);
                ull xs1 = fsplat(x1);
                acc[0][0] = fma2(xs0, wv.x, acc[0][0]);
                acc[0][1] = fma2(xs0, wv.y, acc[0][1]);
                acc[1][0] = fma2(xs1, wv.x, acc[1][0]);
                acc[1][1] = fma2(xs1, wv.y, acc[1][1]);
            }
        }
        __syncthreads();
    }
    // Final barrier above: all GEMM reads of sX buffer 0 completed at the
    // ch=7 sync (last chunk computes from buffer 1) -> buffer 0 reusable as sM.

    float bb[4];
#pragma unroll
    for (int j = 0; j < 4; j++) bb[j] = Bias[s * 16 + (cg << 2) + j];

    // --- Envelope + M assembly: two rows, 4 columns each ---
#pragma unroll
    for (int ri = 0; ri < 2; ri++) {
        const int lrow = row0 + ri;
        const float4* rp = (const float4*)(R + ((size_t)blk * 128 + lrow) * 24);
        float rv[24];
#pragma unroll
        for (int qq = 0; qq < 6; qq++) {
            float4 t = rp[qq];
            rv[qq*4+0] = t.x; rv[qq*4+1] = t.y; rv[qq*4+2] = t.z; rv[qq*4+3] = t.w;
        }
        float env[4] = {0.0f, 0.0f, 0.0f, 0.0f};
#pragma unroll
        for (int i = 0; i < 8; i++) {
            float px = rv[i*3 + 0];
            float py = rv[i*3 + 1];
            float pz = rv[i*3 + 2];
#pragma unroll
            for (int cj = 0; cj < 4; cj++) {
                int gi = s * 128 + i * 16 + (cg << 2) + cj;
                float4 ga = *(const float4*)(sG + gi * 8);      // gxx,gyy,gzz,2gxy
                float4 gb = *(const float4*)(sG + gi * 8 + 4);  // 2gxz,2gyz,ion,pad
                float q1 = px * (ga.x * px + ga.w * py + gb.x * pz)
                         + py * (ga.y * py + gb.y * pz)
                         + pz * (ga.z * pz);
                float rl;
                asm("sqrt.approx.f32 %0, %1;" : "=f"(rl) : "f"(q1));
                env[cj] += __expf(-rl) * gb.z;
            }
        }
        float* mrow = sM + lrow * 17 + (cg << 2);
        mrow[0] = (pklo(acc[ri][0]) + bb[0]) * env[0];
        mrow[1] = (pkhi(acc[ri][0]) + bb[1]) * env[1];
        mrow[2] = (pklo(acc[ri][1]) + bb[2]) * env[2];
        mrow[3] = (pkhi(acc[ri][1]) + bb[3]) * env[3];
    }
    __syncthreads();

    // ======================= phase 2: cofactors ===========================
    // 8 matrices (4 batches x 2 spins); matrix lmat rows at sM[lmat*16+n][.].
    // One matrix per 16-lane half-warp -> warps 0..3 (threads 0..127).
    if (tid < 128) {
        const unsigned FULL = 0xffffffffu;
        const int lmat = tid >> 4;
        const int r    = tid & 15;                 // row of A (= column of M)
        const unsigned hmask = 0xFFFFu << (tid & 16);
        float* pb = sP + lmat * 18;
        const float* Mb = sM + lmat * 16 * 17;     // this matrix's 16 rows

        float a[16];
#pragma unroll
        for (int c = 0; c < 16; c++) a[c] = Mb[c * 17 + r];  // A[r][c] = M[c][r]
        float rhs = (r == 0) ? 1.0f : 0.0f;
        float mi0 = Mb[r * 17];                    // M[r][0]

        float det = 1.0f;
        int  sstep = 16;
        int  myp   = 0;
        bool elim  = false;

#pragma unroll
        for (int k = 0; k < 16; k++) {
            unsigned keyv = 0u;
            if (!elim) {
                unsigned mb = __float_as_uint(fabsf(a[k]));
                keyv = (mb & 0xFFFFFFE0u) | 0x10u | (unsigned)r;
            }
            unsigned best = __reduce_max_sync(hmask, keyv);
            int p = (int)(best & 15u);
            if (k == r) myp = p;
            bool ispiv = (r == p);

            if (ispiv) {
                float pv  = a[k];
                float inv = 1.0f / pv;
                pb[17] = pv;
#pragma unroll
                for (int c = k + 1; c < 16; c++) { a[c] *= inv; pb[c] = a[c]; }
                rhs *= inv;
                pb[16] = rhs;
                elim  = true;
                sstep = k;
            }
            __syncwarp(FULL);

            det *= pb[17];

            if (!ispiv) {
                float f = a[k];
#pragma unroll
                for (int c = k + 1; c < 16; c++) a[c] = fmaf(-f, pb[c], a[c]);
                rhs = fmaf(-f, pb[16], rhs);
            }
            __syncwarp(FULL);
        }

        // Permutation parity via inversion count of sstep sequence
        int invc = 0;
#pragma unroll
        for (int j = 0; j < 16; j++) {
            int sj = __shfl_sync(FULL, sstep, j, 16);
            if (j > r && sj < sstep) invc++;
        }
#pragma unroll
        for (int off = 8; off > 0; off >>= 1) invc += __shfl_xor_sync(FULL, invc, off, 16);
        if (invc & 1) det = -det;

        float z = __shfl_sync(FULL, rhs, myp, 16);

        out[((size_t)blk * 8 + lmat) * 16 + r] = mi0 * det * z;
    }
}

// ---------------------------------------------------------------------------
extern "C" void kernel_launch(void* const* d_in, const int* in_sizes, int n_in,
                              void* d_out, int out_size) {
    const float* X    = (const float*)d_in[0];   // eq_inputs [B][32][256]
    const float* R    = (const float*)d_in[1];   // r_ei      [B][32][8][3]
    const float* W    = (const float*)d_in[2];   // W         [2][256][16]
    const float* Bias = (const float*)d_in[3];   // b         [2][16]
    const float* ED   = (const float*)d_in[4];   // env_dim   [2][8][16][3][3]
    const float* EI   = (const float*)d_in[5];   // env_ion   [2][8][16]
    float* out = (float*)d_out;

    int B = in_sizes[0] / (32 * 256);            // 4096
    if (B > BMAX) B = BMAX;

    // Idempotent attribute set for >48KB dynamic smem (no allocation involved)
    cudaFuncSetAttribute(fused_kernel,
                         cudaFuncAttributeMaxDynamicSharedMemorySize, SMEM_BYTES);

    fused_kernel<<<B / 4, 256, SMEM_BYTES>>>(X, R, W, Bias, ED, EI, out);
    (void)n_in; (void)out_size;
}